// round 14
// baseline (speedup 1.0000x reference)
#include <cuda_runtime.h>
#include <cuda_fp16.h>

// ---------------- problem constants ----------------
#define K_CODES 512
#define D_DIM   64
#define NPTS    65536          // 64*32*32
#define HW      1024           // 32*32
#define CHW     65536          // 64*1024
#define BETA_C  0.25f
#define DECAY_C 0.99f
#define OMD_C   0.01f
#define EPS_C   1e-5f
#define TAU     1e-4f          // rescue threshold (>3x worst-case fp16 3-term error)

// output layout (float32, tuple order)
#define OFF_Q    1
#define OFF_PERP 4194305
#define OFF_IDX  4194306
#define OFF_CS   4259842
#define OFF_W    4260354
#define OFF_E    4293122

// ---------------- scratch (zero-init at load; kernels restore zero) --------
__device__ float g_counts[K_CODES];
__device__ float g_dw[K_CODES * D_DIM];
__device__ float g_loss_acc;
__device__ float g_perp_acc;
__device__ int   g_done;
__device__ int   g_rescue_pts[NPTS];
__device__ int   g_rescue_cnt;

// ---------------- helpers ----------------
__device__ __forceinline__ void red_add_v4(float* p, float a, float b, float c, float d) {
    asm volatile("red.global.add.v4.f32 [%0], {%1, %2, %3, %4};"
                 :: "l"(p), "f"(a), "f"(b), "f"(c), "f"(d) : "memory");
}
__device__ __forceinline__ unsigned smem_u32(const void* p) {
    unsigned a;
    asm("{ .reg .u64 t; cvta.to.shared.u64 t, %1; cvt.u32.u64 %0, t; }" : "=r"(a) : "l"(p));
    return a;
}
__device__ __forceinline__ unsigned pack_hf(__half a, __half b) {
    return (unsigned)__half_as_ushort(a) | ((unsigned)__half_as_ushort(b) << 16);
}
// split fp32 -> (hi fp16, lo fp16) packed pair of two values
__device__ __forceinline__ void split2(float v0, float v1, unsigned& h, unsigned& l) {
    __half h0 = __float2half(v0), h1 = __float2half(v1);
    __half l0 = __float2half(v0 - __half2float(h0));
    __half l1 = __float2half(v1 - __half2float(h1));
    h = pack_hf(h0, h1);
    l = pack_hf(l0, l1);
}
// monotonic float -> orderable uint mapping
__device__ __forceinline__ unsigned f2ord(float f) {
    unsigned u = __float_as_uint(f);
    return (u & 0x80000000u) ? ~u : (u | 0x80000000u);
}
__device__ __forceinline__ float2 h2f2(unsigned u) {
    __half2 h = *reinterpret_cast<__half2*>(&u);
    return __half22float2(h);
}
#define SW128(o) ((o) ^ (((o) >> 3) & 0x70))

// fp32-accum fp16 MMA (sm_80+ baseline PTX)
__device__ __forceinline__ void mma_f16(float* c, const unsigned* a,
                                        unsigned b0, unsigned b1) {
    asm volatile(
        "mma.sync.aligned.m16n8k16.row.col.f32.f16.f16.f32 "
        "{%0,%1,%2,%3}, {%4,%5,%6,%7}, {%8,%9}, {%0,%1,%2,%3};"
        : "+f"(c[0]), "+f"(c[1]), "+f"(c[2]), "+f"(c[3])
        : "r"(a[0]), "r"(a[1]), "r"(a[2]), "r"(a[3]), "r"(b0), "r"(b1));
}
__device__ __forceinline__ void ldmx4(unsigned& r0, unsigned& r1,
                                      unsigned& r2, unsigned& r3, unsigned saddr) {
    asm volatile("ldmatrix.sync.aligned.m8n8.x4.shared.b16 {%0,%1,%2,%3}, [%4];"
                 : "=r"(r0), "=r"(r1), "=r"(r2), "=r"(r3) : "r"(saddr));
}
__device__ __forceinline__ void upd(float& best, float& sec, int& idx, float d, int c) {
    if (d < best) { sec = best; best = d; idx = c; }
    else if (d < sec) { sec = d; }
}

// ---------------- K1: fused convert + GEMM + argmin + epilogue -------------
// 128 CTAs x 1024 thr (32 warps). Each warp: 16 points (one m16 tile), 512 codes.
// smem: nrm 2KB @0 | idx 2KB @2048 | Bh 64KB @4096 | Bl 64KB @69632 -> 135168 B
#define SM_NRM 0
#define SM_IDX 2048
#define SM_BH  4096
#define SM_BL  69632
#define SMEM_SZ 135168

__global__ __launch_bounds__(1024, 1)
void vq_fused(const float* __restrict__ in, const float* __restrict__ emb,
              float* __restrict__ out_q, float* __restrict__ out_idx) {
    extern __shared__ char smem[];
    const unsigned sb = smem_u32(smem);
    float* nrm_sh = (float*)(smem + SM_NRM);
    int*   sidx   = (int*)(smem + SM_IDX);
    const int tid  = threadIdx.x;
    const int wid  = tid >> 5;
    const int lane = tid & 31;

    // ---- stage B: two threads per codebook row -> fp16 h/l swizzled smem
    {
        const int row = tid >> 1;            // 0..511
        const int uo  = (tid & 1) * 4;       // chunk offset 0 or 4
        const float4* er = (const float4*)(emb + row * D_DIM);
        float s = 0.0f;
        #pragma unroll
        for (int u = 0; u < 4; ++u) {
            const int uu = uo + u;
            float4 e0 = __ldg(er + 2 * uu);
            float4 e1 = __ldg(er + 2 * uu + 1);
            s = fmaf(e0.x, e0.x, s); s = fmaf(e0.y, e0.y, s);
            s = fmaf(e0.z, e0.z, s); s = fmaf(e0.w, e0.w, s);
            s = fmaf(e1.x, e1.x, s); s = fmaf(e1.y, e1.y, s);
            s = fmaf(e1.z, e1.z, s); s = fmaf(e1.w, e1.w, s);
            uint4 hq, lq;
            split2(e0.x, e0.y, hq.x, lq.x);
            split2(e0.z, e0.w, hq.y, lq.y);
            split2(e1.x, e1.y, hq.z, lq.z);
            split2(e1.z, e1.w, hq.w, lq.w);
            const unsigned off = SW128((unsigned)(row * 128 + uu * 16));
            *(uint4*)(smem + SM_BH + off) = hq;
            *(uint4*)(smem + SM_BL + off) = lq;
        }
        const float so = __shfl_xor_sync(0xFFFFFFFFu, s, 1);
        if ((tid & 1) == 0) nrm_sh[row] = s + so;
    }
    __syncthreads();

    const int r     = lane & 7;
    const int half_ = (lane >> 3) & 1;
    const unsigned qk = lane & 3;
    const unsigned qr = lane >> 2;
    // lanes 0-15 source BH (h fragments), lanes 16-31 source BL (l fragments)
    const unsigned bbase = sb + ((lane & 16) ? SM_BL : SM_BH) + (unsigned)(r * 128);

    const int p0  = blockIdx.x * 512 + wid * 16;   // 16 points per warp
    const int b   = p0 >> 10;
    const int hw0 = p0 & 1023;

    // ---- A fragments straight from fp32 NCHW input, split h/l (one tile)
    unsigned ah[16], al[16];
    {
        const int hwA = hw0 + (int)qr;      // row qr
        const int hwB = hwA + 8;            // row qr+8
        const float* base = in + (size_t)b * CHW;
        #pragma unroll
        for (int kk = 0; kk < 4; ++kk) {
            const int c0 = kk * 16 + 2 * (int)qk;
            const int c8 = c0 + 8;
            split2(base[(c0    ) * HW + hwA], base[(c0 + 1) * HW + hwA],
                   ah[kk*4+0], al[kk*4+0]);
            split2(base[(c0    ) * HW + hwB], base[(c0 + 1) * HW + hwB],
                   ah[kk*4+1], al[kk*4+1]);
            split2(base[(c8    ) * HW + hwA], base[(c8 + 1) * HW + hwA],
                   ah[kk*4+2], al[kk*4+2]);
            split2(base[(c8    ) * HW + hwB], base[(c8 + 1) * HW + hwB],
                   ah[kk*4+3], al[kk*4+3]);
        }
    }

    // per-kk swizzled column offsets (loop-invariant)
    unsigned kx[4];
    #pragma unroll
    for (int kk = 0; kk < 4; ++kk)
        kx[kk] = ((unsigned)(kk * 32 + half_ * 16)) ^ (unsigned)(r * 16);

    // slot s: 0 = row qr, 1 = row qr+8
    float best[2] = {3.4e38f, 3.4e38f};
    float sec [2] = {3.4e38f, 3.4e38f};
    int   idx [2] = {0, 0};

    #pragma unroll 1
    for (int nt = 0; nt < 64; ++nt) {
        float cm[4] = {0.f, 0.f, 0.f, 0.f};   // h.eh chain
        float cc[4] = {0.f, 0.f, 0.f, 0.f};   // corrections chain
        const unsigned ntoff = bbase + (unsigned)(nt * 1024);
        #pragma unroll
        for (int kk = 0; kk < 4; ++kk) {
            unsigned b0, b1, b2, b3;           // b0,b1 = eh ; b2,b3 = el
            ldmx4(b0, b1, b2, b3, ntoff + kx[kk]);
            mma_f16(cm, &ah[kk*4], b0, b1);    // h.eh
            mma_f16(cc, &ah[kk*4], b2, b3);    // h.el
            mma_f16(cc, &al[kk*4], b0, b1);    // l.eh
        }
        const int colb = nt * 8 + 2 * (int)qk;
        const float n0 = nrm_sh[colb];
        const float n1 = nrm_sh[colb + 1];
        upd(best[0], sec[0], idx[0], fmaf(-2.f, cm[0] + cc[0], n0), colb);
        upd(best[0], sec[0], idx[0], fmaf(-2.f, cm[1] + cc[1], n1), colb + 1);
        upd(best[1], sec[1], idx[1], fmaf(-2.f, cm[2] + cc[2], n0), colb);
        upd(best[1], sec[1], idx[1], fmaf(-2.f, cm[3] + cc[3], n1), colb + 1);
    }

    // merge across the 4 lanes of each quad
    #pragma unroll
    for (int s = 0; s < 2; ++s) {
        #pragma unroll
        for (int o = 1; o <= 2; o <<= 1) {
            float ob = __shfl_xor_sync(0xFFFFFFFFu, best[s], o);
            float os = __shfl_xor_sync(0xFFFFFFFFu, sec[s],  o);
            int   oi = __shfl_xor_sync(0xFFFFFFFFu, idx[s],  o);
            if (ob < best[s] || (ob == best[s] && oi < idx[s])) {
                sec[s] = fminf(best[s], os); best[s] = ob; idx[s] = oi;
            } else sec[s] = fminf(sec[s], ob);
        }
    }

    if (qk == 0) {
        #pragma unroll
        for (int s = 0; s < 2; ++s) {
            const int lp = wid * 16 + (int)qr + s * 8;
            const int p  = blockIdx.x * 512 + lp;
            out_idx[p] = (float)idx[s];
            const bool resc = (sec[s] - best[s] < TAU);
            sidx[lp] = idx[s] | (resc ? 0x80000000 : 0);
            if (resc) {
                int slot = atomicAdd(&g_rescue_cnt, 1);
                g_rescue_pts[slot] = p;
            }
        }
    }
    __syncthreads();

    // ---- fused epilogue: two threads per point (32 channels each)
    //      e reconstructed from smem: e = fp32(h) + fp32(l)  (err ~2.4e-7|e|)
    {
        const int lp = tid & 511;
        const int hf = tid >> 9;                  // 0 or 1 (uniform per warp)
        const int p  = blockIdx.x * 512 + lp;
        const int bb = p >> 10, hw = p & 1023;
        const float* xin = in + (size_t)bb * CHW + hw;
        const int v = sidx[lp];
        float lsum = 0.0f;
        if (v >= 0) {
            float* qout  = out_q + (size_t)bb * CHW + hw;
            float* dwrow = g_dw + v * D_DIM;
            const unsigned vrow = (unsigned)v * 128u;
            #pragma unroll
            for (int uu = 0; uu < 4; ++uu) {
                const int u = hf * 4 + uu;        // chunk of 8 channels
                const unsigned off = SW128(vrow + (unsigned)(u * 16));
                const uint4 hq = *(const uint4*)(smem + SM_BH + off);
                const uint4 lq = *(const uint4*)(smem + SM_BL + off);
                const float2 ha = h2f2(hq.x), hb = h2f2(hq.y), hc = h2f2(hq.z), hd = h2f2(hq.w);
                const float2 la = h2f2(lq.x), lb = h2f2(lq.y), lc = h2f2(lq.z), ld = h2f2(lq.w);
                const float e0 = ha.x + la.x, e1 = ha.y + la.y;
                const float e2 = hb.x + lb.x, e3 = hb.y + lb.y;
                const float e4 = hc.x + lc.x, e5 = hc.y + lc.y;
                const float e6 = hd.x + ld.x, e7 = hd.y + ld.y;
                const int c = u * 8;
                const float x0 = xin[(c+0)*HW], x1 = xin[(c+1)*HW];
                const float x2 = xin[(c+2)*HW], x3 = xin[(c+3)*HW];
                const float x4 = xin[(c+4)*HW], x5 = xin[(c+5)*HW];
                const float x6 = xin[(c+6)*HW], x7 = xin[(c+7)*HW];
                const float d0 = e0-x0, d1 = e1-x1, d2 = e2-x2, d3 = e3-x3;
                const float d4 = e4-x4, d5 = e5-x5, d6 = e6-x6, d7 = e7-x7;
                qout[(c+0)*HW] = x0+d0; qout[(c+1)*HW] = x1+d1;
                qout[(c+2)*HW] = x2+d2; qout[(c+3)*HW] = x3+d3;
                qout[(c+4)*HW] = x4+d4; qout[(c+5)*HW] = x5+d5;
                qout[(c+6)*HW] = x6+d6; qout[(c+7)*HW] = x7+d7;
                lsum = fmaf(d0,d0,lsum); lsum = fmaf(d1,d1,lsum);
                lsum = fmaf(d2,d2,lsum); lsum = fmaf(d3,d3,lsum);
                lsum = fmaf(d4,d4,lsum); lsum = fmaf(d5,d5,lsum);
                lsum = fmaf(d6,d6,lsum); lsum = fmaf(d7,d7,lsum);
                red_add_v4(dwrow + c,     x0, x1, x2, x3);
                red_add_v4(dwrow + c + 4, x4, x5, x6, x7);
            }
            if (hf == 0) atomicAdd(&g_counts[v], 1.0f);
        }
        #pragma unroll
        for (int o = 16; o > 0; o >>= 1) lsum += __shfl_xor_sync(0xFFFFFFFFu, lsum, o);
        if (lane == 0) atomicAdd(&g_loss_acc, lsum);
    }
}

// ---------------- K2: exact fp32 rescue + full epilogue, one CTA per point -
__global__ __launch_bounds__(256)
void vq_rescue(const float* __restrict__ in, const float* __restrict__ emb,
               float* __restrict__ out_idx, float* __restrict__ out_q) {
    __shared__ float xs[D_DIM];
    __shared__ unsigned long long red[256];
    const int tid = threadIdx.x;
    const int cnt = g_rescue_cnt;

    for (int itm = blockIdx.x; itm < cnt; itm += gridDim.x) {
        const int p  = g_rescue_pts[itm];
        const int b  = p >> 10, hw = p & 1023;
        if (tid < D_DIM) xs[tid] = __ldg(in + (size_t)b * CHW + tid * HW + hw);
        __syncthreads();

        unsigned long long bestp = ~0ull;
        #pragma unroll
        for (int cc = 0; cc < 2; ++cc) {
            const int code = cc * 256 + tid;
            const float4* er = (const float4*)(emb + code * D_DIM);
            float s = 0.0f;
            #pragma unroll
            for (int j = 0; j < 16; ++j) {
                float4 e4 = __ldg(er + j);
                float d0 = xs[4 * j + 0] - e4.x;
                float d1 = xs[4 * j + 1] - e4.y;
                float d2 = xs[4 * j + 2] - e4.z;
                float d3 = xs[4 * j + 3] - e4.w;
                s = fmaf(d0, d0, s); s = fmaf(d1, d1, s);
                s = fmaf(d2, d2, s); s = fmaf(d3, d3, s);
            }
            const unsigned long long pk =
                ((unsigned long long)f2ord(s) << 32) | (unsigned)code;
            bestp = (pk < bestp) ? pk : bestp;
        }
        red[tid] = bestp;
        __syncthreads();
        #pragma unroll
        for (int o = 128; o > 0; o >>= 1) {
            if (tid < o) {
                unsigned long long v = red[tid + o];
                if (v < red[tid]) red[tid] = v;
            }
            __syncthreads();
        }
        const int bi = (int)(unsigned)(red[0] & 0xffffffffu);

        // full epilogue for this rescued point
        if (tid == 0) {
            out_idx[p] = (float)bi;
            atomicAdd(&g_counts[bi], 1.0f);
        }
        float lsum = 0.0f;
        if (tid < D_DIM) {
            const float e = __ldg(emb + bi * D_DIM + tid);
            const float x = xs[tid];
            const float d = e - x;
            out_q[(size_t)b * CHW + tid * HW + hw] = x + d;
            atomicAdd(&g_dw[bi * D_DIM + tid], x);
            lsum = d * d;
        }
        if (tid < D_DIM) {
            #pragma unroll
            for (int o = 16; o > 0; o >>= 1)
                lsum += __shfl_xor_sync(0xFFFFFFFFu, lsum, o);
            if ((tid & 31) == 0) atomicAdd(&g_loss_acc, lsum);
        }
        __syncthreads();
    }
}

// ---------------- K3: merged finalize (grid 64 x 512) ----------------------
// n = DECAY*sum(ema_cs) + OMD*NPTS  (since sum(counts) == NPTS identically)
__global__ __launch_bounds__(512, 1)
void vq_fin(const float* __restrict__ ema_cs, const float* __restrict__ ema_w,
            float* __restrict__ out) {
    __shared__ float red[512];
    __shared__ float s_ncs[8];
    __shared__ float s_plp[8];
    const int tid = threadIdx.x;
    const int j   = blockIdx.x;

    red[tid] = __ldg(ema_cs + tid);
    __syncthreads();
    #pragma unroll
    for (int o = 256; o > 0; o >>= 1) {
        if (tid < o) red[tid] += red[tid + o];
        __syncthreads();
    }
    const float n = DECAY_C * red[0] + OMD_C * (float)NPTS;

    if (tid < 8) {
        const int k = j * 8 + tid;
        const float cnt = g_counts[k];
        g_counts[k] = 0.0f;                            // block-owned, safe
        const float raw = __ldg(ema_cs + k) * DECAY_C + OMD_C * cnt;
        const float ncs = (raw + EPS_C) / (n + (float)K_CODES * EPS_C) * n;
        s_ncs[tid] = ncs;
        out[OFF_CS + k] = ncs;
        const float pr = cnt * (1.0f / (float)NPTS);
        s_plp[tid] = pr * logf(pr + 1e-10f);
    }
    __syncthreads();

    if (tid == 0) {
        float part = 0.0f;
        #pragma unroll
        for (int t = 0; t < 8; ++t) part += s_plp[t];
        atomicAdd(&g_perp_acc, part);
        __threadfence();
        const int d = atomicAdd(&g_done, 1);
        if (d == 63) {                                  // last block finalizes
            const float perp = atomicAdd(&g_perp_acc, 0.0f);
            out[OFF_PERP] = expf(-perp);
            out[0] = BETA_C * g_loss_acc / (float)(NPTS * D_DIM);
            g_loss_acc   = 0.0f;
            g_perp_acc   = 0.0f;
            g_done       = 0;
            g_rescue_cnt = 0;
        }
    }

    const int i = j * 512 + tid;                        // < 32768
    const float w = __ldg(ema_w + i) * DECAY_C + OMD_C * g_dw[i];
    g_dw[i] = 0.0f;
    out[OFF_W + i] = w;
    out[OFF_E + i] = w / s_ncs[tid >> 6];
}

// ---------------- launch ----------------
extern "C" void kernel_launch(void* const* d_in, const int* in_sizes, int n_in,
                              void* d_out, int out_size) {
    const float* in     = (const float*)d_in[0];
    const float* emb    = (const float*)d_in[1];
    const float* ema_w  = (const float*)d_in[2];
    const float* ema_cs = (const float*)d_in[3];
    float* out = (float*)d_out;

    cudaFuncSetAttribute(vq_fused,
                         cudaFuncAttributeMaxDynamicSharedMemorySize, SMEM_SZ);

    vq_fused<<<128, 1024, SMEM_SZ>>>(in, emb, out + OFF_Q, out + OFF_IDX);
    vq_rescue<<<128, 256>>>(in, emb, out + OFF_IDX, out + OFF_Q);
    vq_fin<<<64, 512>>>(ema_cs, ema_w, out);
}

// round 15
// speedup vs baseline: 1.0526x; 1.0526x over previous
#include <cuda_runtime.h>
#include <cuda_fp16.h>

// ---------------- problem constants ----------------
#define K_CODES 512
#define D_DIM   64
#define NPTS    65536          // 64*32*32
#define HW      1024           // 32*32
#define CHW     65536          // 64*1024
#define BETA_C  0.25f
#define DECAY_C 0.99f
#define OMD_C   0.01f
#define EPS_C   1e-5f
#define TAU     1e-4f          // rescue threshold (>3x worst-case fp16 3-term error)

#define PTS_CTA 448            // 28 warps x 16 points
#define NCTAS   147            // ceil(65536/448); last CTA has 128 points
#define NTHR    896

// output layout (float32, tuple order)
#define OFF_Q    1
#define OFF_PERP 4194305
#define OFF_IDX  4194306
#define OFF_CS   4259842
#define OFF_W    4260354
#define OFF_E    4293122

// ---------------- scratch (zero-init at load; kernels restore zero) --------
__device__ float g_counts[K_CODES];
__device__ float g_dw[K_CODES * D_DIM];
__device__ float g_loss_acc;
__device__ float g_perp_acc;
__device__ int   g_done;
__device__ int   g_rescue_pts[NPTS];
__device__ int   g_rescue_cnt;

// ---------------- helpers ----------------
__device__ __forceinline__ void red_add_v4(float* p, float a, float b, float c, float d) {
    asm volatile("red.global.add.v4.f32 [%0], {%1, %2, %3, %4};"
                 :: "l"(p), "f"(a), "f"(b), "f"(c), "f"(d) : "memory");
}
__device__ __forceinline__ unsigned smem_u32(const void* p) {
    unsigned a;
    asm("{ .reg .u64 t; cvta.to.shared.u64 t, %1; cvt.u32.u64 %0, t; }" : "=r"(a) : "l"(p));
    return a;
}
__device__ __forceinline__ unsigned pack_hf(__half a, __half b) {
    return (unsigned)__half_as_ushort(a) | ((unsigned)__half_as_ushort(b) << 16);
}
// split fp32 -> (hi fp16, lo fp16) packed pair of two values
__device__ __forceinline__ void split2(float v0, float v1, unsigned& h, unsigned& l) {
    __half h0 = __float2half(v0), h1 = __float2half(v1);
    __half l0 = __float2half(v0 - __half2float(h0));
    __half l1 = __float2half(v1 - __half2float(h1));
    h = pack_hf(h0, h1);
    l = pack_hf(l0, l1);
}
// monotonic float -> orderable uint mapping
__device__ __forceinline__ unsigned f2ord(float f) {
    unsigned u = __float_as_uint(f);
    return (u & 0x80000000u) ? ~u : (u | 0x80000000u);
}
__device__ __forceinline__ float2 h2f2(unsigned u) {
    __half2 h = *reinterpret_cast<__half2*>(&u);
    return __half22float2(h);
}
#define SW128(o) ((o) ^ (((o) >> 3) & 0x70))

// fp32-accum fp16 MMA (sm_80+ baseline PTX)
__device__ __forceinline__ void mma_f16(float* c, const unsigned* a,
                                        unsigned b0, unsigned b1) {
    asm volatile(
        "mma.sync.aligned.m16n8k16.row.col.f32.f16.f16.f32 "
        "{%0,%1,%2,%3}, {%4,%5,%6,%7}, {%8,%9}, {%0,%1,%2,%3};"
        : "+f"(c[0]), "+f"(c[1]), "+f"(c[2]), "+f"(c[3])
        : "r"(a[0]), "r"(a[1]), "r"(a[2]), "r"(a[3]), "r"(b0), "r"(b1));
}
__device__ __forceinline__ void ldmx4(unsigned& r0, unsigned& r1,
                                      unsigned& r2, unsigned& r3, unsigned saddr) {
    asm volatile("ldmatrix.sync.aligned.m8n8.x4.shared.b16 {%0,%1,%2,%3}, [%4];"
                 : "=r"(r0), "=r"(r1), "=r"(r2), "=r"(r3) : "r"(saddr));
}
__device__ __forceinline__ void upd(float& best, float& sec, int& idx, float d, int c) {
    if (d < best) { sec = best; best = d; idx = c; }
    else if (d < sec) { sec = d; }
}

// ---------------- K1: fused convert + GEMM + argmin + epilogue -------------
// 147 CTAs x 896 thr (28 warps). Each warp: 16 points, 512 codes. Last CTA: 128 pts.
// smem: nrm 2KB @0 | idx 2KB @2048 | Bh 64KB @4096 | Bl 64KB @69632 -> 135168 B
#define SM_NRM 0
#define SM_IDX 2048
#define SM_BH  4096
#define SM_BL  69632
#define SMEM_SZ 135168

__global__ __launch_bounds__(NTHR, 1)
void vq_fused(const float* __restrict__ in, const float* __restrict__ emb,
              float* __restrict__ out_q, float* __restrict__ out_idx) {
    extern __shared__ char smem[];
    const unsigned sb = smem_u32(smem);
    float* nrm_sh = (float*)(smem + SM_NRM);
    int*   sidx   = (int*)(smem + SM_IDX);
    const int tid  = threadIdx.x;
    const int wid  = tid >> 5;
    const int lane = tid & 31;

    const int pbase = blockIdx.x * PTS_CTA;
    const int ncta  = min(PTS_CTA, NPTS - pbase);   // 448 or 128 (last CTA)

    // ---- stage B: threads 0-511 each convert one codebook row
    if (tid < K_CODES) {
        const float4* er = (const float4*)(emb + tid * D_DIM);
        float s = 0.0f;
        #pragma unroll
        for (int u = 0; u < 8; ++u) {
            float4 e0 = __ldg(er + 2 * u);
            float4 e1 = __ldg(er + 2 * u + 1);
            s = fmaf(e0.x, e0.x, s); s = fmaf(e0.y, e0.y, s);
            s = fmaf(e0.z, e0.z, s); s = fmaf(e0.w, e0.w, s);
            s = fmaf(e1.x, e1.x, s); s = fmaf(e1.y, e1.y, s);
            s = fmaf(e1.z, e1.z, s); s = fmaf(e1.w, e1.w, s);
            uint4 hq, lq;
            split2(e0.x, e0.y, hq.x, lq.x);
            split2(e0.z, e0.w, hq.y, lq.y);
            split2(e1.x, e1.y, hq.z, lq.z);
            split2(e1.z, e1.w, hq.w, lq.w);
            const unsigned off = SW128((unsigned)(tid * 128 + u * 16));
            *(uint4*)(smem + SM_BH + off) = hq;
            *(uint4*)(smem + SM_BL + off) = lq;
        }
        nrm_sh[tid] = s;
    }
    __syncthreads();

    const int r     = lane & 7;
    const int half_ = (lane >> 3) & 1;
    const unsigned qk = lane & 3;
    const unsigned qr = lane >> 2;
    // lanes 0-15 source BH (matrices 0,1), lanes 16-31 source BL (matrices 2,3)
    const unsigned bbase = sb + ((lane & 16) ? SM_BL : SM_BH) + (unsigned)(r * 128);

    const int p0 = pbase + wid * 16;                // 16 points per warp
    const bool active = (wid * 16) < ncta;

    // per-kk swizzled column offsets (loop-invariant)
    unsigned kx[4];
    #pragma unroll
    for (int kk = 0; kk < 4; ++kk)
        kx[kk] = ((unsigned)(kk * 32 + half_ * 16)) ^ (unsigned)(r * 16);

    if (active) {
        const int b   = p0 >> 10;
        const int hw0 = p0 & 1023;

        // ---- A fragments straight from fp32 NCHW input, split h/l
        unsigned ah[16], al[16];
        {
            const int hwA = hw0 + (int)qr;
            const int hwB = hwA + 8;
            const float* base = in + (size_t)b * CHW;
            #pragma unroll
            for (int kk = 0; kk < 4; ++kk) {
                const int c0 = kk * 16 + 2 * (int)qk;
                const int c8 = c0 + 8;
                split2(base[(c0    ) * HW + hwA], base[(c0 + 1) * HW + hwA],
                       ah[kk*4+0], al[kk*4+0]);
                split2(base[(c0    ) * HW + hwB], base[(c0 + 1) * HW + hwB],
                       ah[kk*4+1], al[kk*4+1]);
                split2(base[(c8    ) * HW + hwA], base[(c8 + 1) * HW + hwA],
                       ah[kk*4+2], al[kk*4+2]);
                split2(base[(c8    ) * HW + hwB], base[(c8 + 1) * HW + hwB],
                       ah[kk*4+3], al[kk*4+3]);
            }
        }

        float best[2] = {3.4e38f, 3.4e38f};
        float sec [2] = {3.4e38f, 3.4e38f};
        int   idx [2] = {0, 0};

        #pragma unroll 2
        for (int nt = 0; nt < 64; ++nt) {
            float cm[4] = {0.f, 0.f, 0.f, 0.f};
            float cc[4] = {0.f, 0.f, 0.f, 0.f};
            const unsigned ntoff = bbase + (unsigned)(nt * 1024);
            #pragma unroll
            for (int kk = 0; kk < 4; ++kk) {
                unsigned b0, b1, b2, b3;           // b0,b1 = eh ; b2,b3 = el
                ldmx4(b0, b1, b2, b3, ntoff + kx[kk]);
                mma_f16(cm, &ah[kk*4], b0, b1);    // h.eh
                mma_f16(cc, &ah[kk*4], b2, b3);    // h.el
                mma_f16(cc, &al[kk*4], b0, b1);    // l.eh
            }
            const int colb = nt * 8 + 2 * (int)qk;
            const float n0 = nrm_sh[colb];
            const float n1 = nrm_sh[colb + 1];
            upd(best[0], sec[0], idx[0], fmaf(-2.f, cm[0] + cc[0], n0), colb);
            upd(best[0], sec[0], idx[0], fmaf(-2.f, cm[1] + cc[1], n1), colb + 1);
            upd(best[1], sec[1], idx[1], fmaf(-2.f, cm[2] + cc[2], n0), colb);
            upd(best[1], sec[1], idx[1], fmaf(-2.f, cm[3] + cc[3], n1), colb + 1);
        }

        // merge across the 4 lanes of each quad
        #pragma unroll
        for (int s = 0; s < 2; ++s) {
            #pragma unroll
            for (int o = 1; o <= 2; o <<= 1) {
                float ob = __shfl_xor_sync(0xFFFFFFFFu, best[s], o);
                float os = __shfl_xor_sync(0xFFFFFFFFu, sec[s],  o);
                int   oi = __shfl_xor_sync(0xFFFFFFFFu, idx[s],  o);
                if (ob < best[s] || (ob == best[s] && oi < idx[s])) {
                    sec[s] = fminf(best[s], os); best[s] = ob; idx[s] = oi;
                } else sec[s] = fminf(sec[s], ob);
            }
        }

        if (qk == 0) {
            #pragma unroll
            for (int s = 0; s < 2; ++s) {
                const int lp = wid * 16 + (int)qr + s * 8;
                const int p  = pbase + lp;
                out_idx[p] = (float)idx[s];
                const bool resc = (sec[s] - best[s] < TAU);
                sidx[lp] = idx[s] | (resc ? 0x80000000 : 0);
                if (resc) {
                    int slot = atomicAdd(&g_rescue_cnt, 1);
                    g_rescue_pts[slot] = p;
                }
            }
        }
    }
    __syncthreads();

    // ---- fused epilogue: two threads per point (32 channels each)
    //      e reconstructed from smem: e = fp32(h) + fp32(l)  (err ~2.4e-7|e|)
    {
        const int lp = (tid < PTS_CTA) ? tid : (tid - PTS_CTA);
        const int hf = (tid < PTS_CTA) ? 0 : 1;     // uniform per warp (448 = 14*32)
        float lsum = 0.0f;
        if (lp < ncta) {
            const int p  = pbase + lp;
            const int bb = p >> 10, hw = p & 1023;
            const float* xin = in + (size_t)bb * CHW + hw;
            const int v = sidx[lp];
            if (v >= 0) {
                float* qout  = out_q + (size_t)bb * CHW + hw;
                float* dwrow = g_dw + v * D_DIM;
                const unsigned vrow = (unsigned)v * 128u;
                #pragma unroll
                for (int uu = 0; uu < 4; ++uu) {
                    const int u = hf * 4 + uu;
                    const unsigned off = SW128(vrow + (unsigned)(u * 16));
                    const uint4 hq = *(const uint4*)(smem + SM_BH + off);
                    const uint4 lq = *(const uint4*)(smem + SM_BL + off);
                    const float2 ha = h2f2(hq.x), hb = h2f2(hq.y), hc = h2f2(hq.z), hd = h2f2(hq.w);
                    const float2 la = h2f2(lq.x), lb = h2f2(lq.y), lc = h2f2(lq.z), ld = h2f2(lq.w);
                    const float e0 = ha.x + la.x, e1 = ha.y + la.y;
                    const float e2 = hb.x + lb.x, e3 = hb.y + lb.y;
                    const float e4 = hc.x + lc.x, e5 = hc.y + lc.y;
                    const float e6 = hd.x + ld.x, e7 = hd.y + ld.y;
                    const int c = u * 8;
                    const float x0 = xin[(c+0)*HW], x1 = xin[(c+1)*HW];
                    const float x2 = xin[(c+2)*HW], x3 = xin[(c+3)*HW];
                    const float x4 = xin[(c+4)*HW], x5 = xin[(c+5)*HW];
                    const float x6 = xin[(c+6)*HW], x7 = xin[(c+7)*HW];
                    const float d0 = e0-x0, d1 = e1-x1, d2 = e2-x2, d3 = e3-x3;
                    const float d4 = e4-x4, d5 = e5-x5, d6 = e6-x6, d7 = e7-x7;
                    qout[(c+0)*HW] = x0+d0; qout[(c+1)*HW] = x1+d1;
                    qout[(c+2)*HW] = x2+d2; qout[(c+3)*HW] = x3+d3;
                    qout[(c+4)*HW] = x4+d4; qout[(c+5)*HW] = x5+d5;
                    qout[(c+6)*HW] = x6+d6; qout[(c+7)*HW] = x7+d7;
                    lsum = fmaf(d0,d0,lsum); lsum = fmaf(d1,d1,lsum);
                    lsum = fmaf(d2,d2,lsum); lsum = fmaf(d3,d3,lsum);
                    lsum = fmaf(d4,d4,lsum); lsum = fmaf(d5,d5,lsum);
                    lsum = fmaf(d6,d6,lsum); lsum = fmaf(d7,d7,lsum);
                    red_add_v4(dwrow + c,     x0, x1, x2, x3);
                    red_add_v4(dwrow + c + 4, x4, x5, x6, x7);
                }
                if (hf == 0) atomicAdd(&g_counts[v], 1.0f);
            }
        }
        #pragma unroll
        for (int o = 16; o > 0; o >>= 1) lsum += __shfl_xor_sync(0xFFFFFFFFu, lsum, o);
        if (lane == 0 && lsum != 0.0f) atomicAdd(&g_loss_acc, lsum);
    }
}

// ---------------- K2: exact fp32 rescue + full epilogue, one CTA per point -
__global__ __launch_bounds__(256)
void vq_rescue(const float* __restrict__ in, const float* __restrict__ emb,
               float* __restrict__ out_idx, float* __restrict__ out_q) {
    __shared__ float xs[D_DIM];
    __shared__ unsigned long long red[256];
    const int tid = threadIdx.x;
    const int cnt = g_rescue_cnt;

    for (int itm = blockIdx.x; itm < cnt; itm += gridDim.x) {
        const int p  = g_rescue_pts[itm];
        const int b  = p >> 10, hw = p & 1023;
        if (tid < D_DIM) xs[tid] = __ldg(in + (size_t)b * CHW + tid * HW + hw);
        __syncthreads();

        unsigned long long bestp = ~0ull;
        #pragma unroll
        for (int cc = 0; cc < 2; ++cc) {
            const int code = cc * 256 + tid;
            const float4* er = (const float4*)(emb + code * D_DIM);
            float s = 0.0f;
            #pragma unroll
            for (int j = 0; j < 16; ++j) {
                float4 e4 = __ldg(er + j);
                float d0 = xs[4 * j + 0] - e4.x;
                float d1 = xs[4 * j + 1] - e4.y;
                float d2 = xs[4 * j + 2] - e4.z;
                float d3 = xs[4 * j + 3] - e4.w;
                s = fmaf(d0, d0, s); s = fmaf(d1, d1, s);
                s = fmaf(d2, d2, s); s = fmaf(d3, d3, s);
            }
            const unsigned long long pk =
                ((unsigned long long)f2ord(s) << 32) | (unsigned)code;
            bestp = (pk < bestp) ? pk : bestp;
        }
        red[tid] = bestp;
        __syncthreads();
        #pragma unroll
        for (int o = 128; o > 0; o >>= 1) {
            if (tid < o) {
                unsigned long long v = red[tid + o];
                if (v < red[tid]) red[tid] = v;
            }
            __syncthreads();
        }
        const int bi = (int)(unsigned)(red[0] & 0xffffffffu);

        if (tid == 0) {
            out_idx[p] = (float)bi;
            atomicAdd(&g_counts[bi], 1.0f);
        }
        float lsum = 0.0f;
        if (tid < D_DIM) {
            const float e = __ldg(emb + bi * D_DIM + tid);
            const float x = xs[tid];
            const float d = e - x;
            out_q[(size_t)b * CHW + tid * HW + hw] = x + d;
            atomicAdd(&g_dw[bi * D_DIM + tid], x);
            lsum = d * d;
        }
        if (tid < D_DIM) {
            #pragma unroll
            for (int o = 16; o > 0; o >>= 1)
                lsum += __shfl_xor_sync(0xFFFFFFFFu, lsum, o);
            if ((tid & 31) == 0) atomicAdd(&g_loss_acc, lsum);
        }
        __syncthreads();
    }
}

// ---------------- K3: merged finalize (grid 64 x 512) ----------------------
// n = DECAY*sum(ema_cs) + OMD*NPTS  (since sum(counts) == NPTS identically)
__global__ __launch_bounds__(512, 1)
void vq_fin(const float* __restrict__ ema_cs, const float* __restrict__ ema_w,
            float* __restrict__ out) {
    __shared__ float red[512];
    __shared__ float s_ncs[8];
    __shared__ float s_plp[8];
    const int tid = threadIdx.x;
    const int j   = blockIdx.x;

    red[tid] = __ldg(ema_cs + tid);
    __syncthreads();
    #pragma unroll
    for (int o = 256; o > 0; o >>= 1) {
        if (tid < o) red[tid] += red[tid + o];
        __syncthreads();
    }
    const float n = DECAY_C * red[0] + OMD_C * (float)NPTS;

    if (tid < 8) {
        const int k = j * 8 + tid;
        const float cnt = g_counts[k];
        g_counts[k] = 0.0f;
        const float raw = __ldg(ema_cs + k) * DECAY_C + OMD_C * cnt;
        const float ncs = (raw + EPS_C) / (n + (float)K_CODES * EPS_C) * n;
        s_ncs[tid] = ncs;
        out[OFF_CS + k] = ncs;
        const float pr = cnt * (1.0f / (float)NPTS);
        s_plp[tid] = pr * logf(pr + 1e-10f);
    }
    __syncthreads();

    if (tid == 0) {
        float part = 0.0f;
        #pragma unroll
        for (int t = 0; t < 8; ++t) part += s_plp[t];
        atomicAdd(&g_perp_acc, part);
        __threadfence();
        const int d = atomicAdd(&g_done, 1);
        if (d == 63) {
            const float perp = atomicAdd(&g_perp_acc, 0.0f);
            out[OFF_PERP] = expf(-perp);
            out[0] = BETA_C * g_loss_acc / (float)(NPTS * D_DIM);
            g_loss_acc   = 0.0f;
            g_perp_acc   = 0.0f;
            g_done       = 0;
            g_rescue_cnt = 0;
        }
    }

    const int i = j * 512 + tid;
    const float w = __ldg(ema_w + i) * DECAY_C + OMD_C * g_dw[i];
    g_dw[i] = 0.0f;
    out[OFF_W + i] = w;
    out[OFF_E + i] = w / s_ncs[tid >> 6];
}

// ---------------- launch ----------------
extern "C" void kernel_launch(void* const* d_in, const int* in_sizes, int n_in,
                              void* d_out, int out_size) {
    const float* in     = (const float*)d_in[0];
    const float* emb    = (const float*)d_in[1];
    const float* ema_w  = (const float*)d_in[2];
    const float* ema_cs = (const float*)d_in[3];
    float* out = (float*)d_out;

    cudaFuncSetAttribute(vq_fused,
                         cudaFuncAttributeMaxDynamicSharedMemorySize, SMEM_SZ);

    vq_fused<<<NCTAS, NTHR, SMEM_SZ>>>(in, emb, out + OFF_Q, out + OFF_IDX);
    vq_rescue<<<128, 256>>>(in, emb, out + OFF_IDX, out + OFF_Q);
    vq_fin<<<64, 512>>>(ema_cs, ema_w, out);
}